// round 6
// baseline (speedup 1.0000x reference)
#include <cuda_runtime.h>
#include <cstdint>

// Scratch (no device allocations) — reset by the last block each run.
static __device__ double   g_acc   = 0.0;
static __device__ unsigned g_count = 0;

__device__ __forceinline__ float fast_tanh(float x) {
    float r; asm("tanh.approx.f32 %0, %1;" : "=f"(r) : "f"(x)); return r;
}

// ---- mbarrier / bulk-copy primitives -------------------------------------
__device__ __forceinline__ void mbar_init(uint32_t a, uint32_t c) {
    asm volatile("mbarrier.init.shared.b64 [%0], %1;" :: "r"(a), "r"(c) : "memory");
}
__device__ __forceinline__ void mbar_expect_tx(uint32_t a, uint32_t b) {
    asm volatile("mbarrier.arrive.expect_tx.shared.b64 _, [%0], %1;" :: "r"(a), "r"(b) : "memory");
}
__device__ __forceinline__ void mbar_arrive(uint32_t a) {
    asm volatile("mbarrier.arrive.shared.b64 _, [%0];" :: "r"(a) : "memory");
}
__device__ __forceinline__ void mbar_wait(uint32_t a, uint32_t parity) {
    uint32_t done;
    asm volatile(
        "{\n\t.reg .pred p;\n\t"
        "mbarrier.try_wait.parity.acquire.cta.shared::cta.b64 p, [%1], %2;\n\t"
        "selp.b32 %0, 1, 0, p;\n\t}"
        : "=r"(done) : "r"(a), "r"(parity) : "memory");
    if (!done) {
        asm volatile(
            "{\n\t.reg .pred P1;\n\t"
            "W_%=:\n\t"
            "mbarrier.try_wait.parity.acquire.cta.shared::cta.b64 P1, [%0], %1, 0x989680;\n\t"
            "@P1 bra.uni D_%=;\n\t"
            "bra.uni W_%=;\n\t"
            "D_%=:\n\t}"
            :: "r"(a), "r"(parity) : "memory");
    }
}
__device__ __forceinline__ void bulk_g2s(uint32_t dst, const void* src,
                                         uint32_t bytes, uint32_t mbar) {
    asm volatile(
        "cp.async.bulk.shared::cluster.global.mbarrier::complete_tx::bytes "
        "[%0], [%1], %2, [%3];"
        :: "r"(dst), "l"(src), "r"(bytes), "r"(mbar) : "memory");
}

// ---- geometry ------------------------------------------------------------
static constexpr int THREADS        = 256;
static constexpr int ROWS_PER_STAGE = 128;
static constexpr int STAGES         = 3;
static constexpr int STAGE_FLOATS   = ROWS_PER_STAGE * 16;            // per tensor
static constexpr int STAGE_BYTES_T  = STAGE_FLOATS * 4;               // 8192
static constexpr int STAGE_TOTAL_F  = 3 * STAGE_FLOATS + ROWS_PER_STAGE; // w,l,s,t
static constexpr int STAGE_TOTAL_B  = STAGE_TOTAL_F * 4;              // 25088
static constexpr int SMEM_BYTES     = STAGES * STAGE_TOTAL_B;         // 75264

// Math per row (K=16), tanh form (validated rel_err 2e-7):
//   row = log(S2/S1) - ln4
//   S1 = sum e^{w}
//   S2 = sum e^{w} * (1/s) * (1 - tanh^2(z/2)),  z=(t-loc)/s
__global__ __launch_bounds__(THREADS, 2) void MixtureOfLogistics_kernel(
    const float* __restrict__ weight,
    const float* __restrict__ loc,
    const float* __restrict__ scale,
    const float* __restrict__ targets,
    float* __restrict__ out,
    int n_stages, double inv_n)
{
    extern __shared__ float smem[];
    __shared__ uint64_t full_bar[STAGES], empty_bar[STAGES];

    const int tid   = threadIdx.x;
    const int lane4 = tid & 3;
    const int grp   = tid >> 2;                 // 0..63

    const uint32_t fb0 = (uint32_t)__cvta_generic_to_shared(&full_bar[0]);
    const uint32_t eb0 = (uint32_t)__cvta_generic_to_shared(&empty_bar[0]);

    if (tid == 0) {
        #pragma unroll
        for (int i = 0; i < STAGES; i++) {
            mbar_init(fb0 + i * 8, 1);
            mbar_init(eb0 + i * 8, THREADS);
        }
    }
    __syncthreads();

    // Number of stages this block handles (grid-stride over stages).
    int nblk = 0;
    for (int s = blockIdx.x; s < n_stages; s += gridDim.x) nblk++;

    // Producer helper: issue bulk loads for local stage it.
    auto issue = [&](int it) {
        const int   gs   = blockIdx.x + it * gridDim.x;        // global stage
        const int   slot = it % STAGES;
        float*      base = smem + slot * STAGE_TOTAL_F;
        const size_t off = (size_t)gs * STAGE_FLOATS;
        const uint32_t mb = fb0 + slot * 8;
        const uint32_t d  = (uint32_t)__cvta_generic_to_shared(base);
        mbar_expect_tx(mb, (uint32_t)STAGE_TOTAL_B);
        bulk_g2s(d,                       weight + off, STAGE_BYTES_T, mb);
        bulk_g2s(d + STAGE_BYTES_T,       loc    + off, STAGE_BYTES_T, mb);
        bulk_g2s(d + 2 * STAGE_BYTES_T,   scale  + off, STAGE_BYTES_T, mb);
        bulk_g2s(d + 3 * STAGE_BYTES_T,
                 targets + (size_t)gs * ROWS_PER_STAGE, ROWS_PER_STAGE * 4, mb);
    };

    if (tid == 0) {                       // prologue: fill lookahead
        if (nblk > 0) issue(0);
        if (nblk > 1) issue(1);
    }

    float acc = 0.0f;

    for (int it = 0; it < nblk; it++) {
        const int slot = it % STAGES;
        if (tid == 0) {
            const int jp = it + 2;
            if (jp < nblk) {
                if (jp >= STAGES)
                    mbar_wait(eb0 + (jp % STAGES) * 8, ((jp / STAGES) - 1) & 1);
                issue(jp);
            }
        }
        mbar_wait(fb0 + slot * 8, (it / STAGES) & 1);

        const float* sw = smem + slot * STAGE_TOTAL_F;
        const float* sl = sw + STAGE_FLOATS;
        const float* ss = sl + STAGE_FLOATS;
        const float* st = ss + STAGE_FLOATS;

        #pragma unroll
        for (int half = 0; half < 2; half++) {
            const int r = grp + half * 64;
            const float t = st[r];
            const int o = r * 16 + lane4 * 4;
            const float4 w4 = *reinterpret_cast<const float4*>(sw + o);
            const float4 l4 = *reinterpret_cast<const float4*>(sl + o);
            const float4 s4 = *reinterpret_cast<const float4*>(ss + o);

            const float w[4] = {w4.x, w4.y, w4.z, w4.w};
            const float l[4] = {l4.x, l4.y, l4.z, l4.w};
            const float s[4] = {s4.x, s4.y, s4.z, s4.w};

            float S1 = 0.0f, S2 = 0.0f;
            #pragma unroll
            for (int c = 0; c < 4; c++) {
                float rs = __fdividef(1.0f, s[c]);            // MUFU rcp
                float th = fast_tanh((t - l[c]) * rs * 0.5f); // MUFU tanh
                float ew = __expf(w[c]);                      // MUFU ex2
                S1 += ew;
                S2 = fmaf(ew * rs, fmaf(-th, th, 1.0f), S2);
            }
            S1 += __shfl_xor_sync(0xffffffffu, S1, 1);
            S1 += __shfl_xor_sync(0xffffffffu, S1, 2);
            S2 += __shfl_xor_sync(0xffffffffu, S2, 1);
            S2 += __shfl_xor_sync(0xffffffffu, S2, 2);

            if (lane4 == 0) {
                S2 = fmaxf(S2, 1e-37f);
                acc += __logf(__fdividef(S2, S1)) - 1.3862943611f;  // - ln4
            }
        }

        mbar_arrive(eb0 + slot * 8);       // free the slot
    }

    // Reduce (lane4==0 lanes hold partials).
    #pragma unroll
    for (int off = 16; off > 0; off >>= 1)
        acc += __shfl_xor_sync(0xffffffffu, acc, off);

    __shared__ float warp_part[8];
    const int warp = tid >> 5, lane = tid & 31;
    if (lane == 0) warp_part[warp] = acc;
    __syncthreads();

    if (warp == 0) {
        float v = (lane < (THREADS >> 5)) ? warp_part[lane] : 0.0f;
        #pragma unroll
        for (int off = 4; off > 0; off >>= 1)
            v += __shfl_xor_sync(0xffffffffu, v, off);
        if (lane == 0) {
            atomicAdd(&g_acc, (double)v);
            __threadfence();
            unsigned done = atomicAdd(&g_count, 1u);
            if (done == gridDim.x - 1) {
                out[0] = (float)(g_acc * inv_n);
                g_acc = 0.0; g_count = 0u;
                __threadfence();
            }
        }
    }
}

extern "C" void kernel_launch(void* const* d_in, const int* in_sizes, int n_in,
                              void* d_out, int out_size) {
    const float* weight  = (const float*)d_in[0];
    const float* loc     = (const float*)d_in[1];
    const float* scale   = (const float*)d_in[2];
    const float* targets = (const float*)d_in[3];
    float* out = (float*)d_out;

    const int n_rows   = in_sizes[3];               // 2,097,152 (mult of 128)
    const int n_stages = n_rows / ROWS_PER_STAGE;   // 16384
    const double inv_n = 1.0 / (double)n_rows;

    static bool attr_set = false;                   // idempotent attribute set
    if (!attr_set) {
        cudaFuncSetAttribute(MixtureOfLogistics_kernel,
                             cudaFuncAttributeMaxDynamicSharedMemorySize,
                             SMEM_BYTES);
        attr_set = true;
    }

    // 2 blocks/SM x 148 SMs, persistent, one wave.
    MixtureOfLogistics_kernel<<<296, THREADS, SMEM_BYTES>>>(
        weight, loc, scale, targets, out, n_stages, inv_n);
}

// round 7
// speedup vs baseline: 1.8621x; 1.8621x over previous
#include <cuda_runtime.h>

// Scratch (no device allocations) — reset by the last block each run,
// so every kernel_launch invocation is deterministic.
static __device__ double   g_acc   = 0.0;
static __device__ unsigned g_count = 0;

__device__ __forceinline__ float fast_tanh(float x) {
    float r; asm("tanh.approx.f32 %0, %1;" : "=f"(r) : "f"(x)); return r;
}

// Math per row (K=16), tanh form (validated rel_err 2e-7 in R5):
//   row = log(S2/S1) - ln4
//   S1 = sum_k e^{w_k}
//   S2 = sum_k e^{w_k} * (1/s_k) * (1 - tanh^2(z_k/2)),  z = (t-loc)/s
// (uses e^m/(1+e^m)^2 = (1 - tanh^2(z/2))/4, even in z -> no fabs).
//
// Layout: 4 lanes per row, one float4 per tensor per lane (warp = 512B dense
// per LDG.128). Software prefetch: next grid-stride iteration's 3 float4 + t
// are loaded BEFORE computing the current one, doubling per-warp outstanding
// load bytes through the compute phase.
__global__ __launch_bounds__(256, 5) void MixtureOfLogistics_kernel(
    const float* __restrict__ weight,
    const float* __restrict__ loc,
    const float* __restrict__ scale,
    const float* __restrict__ targets,
    float* __restrict__ out,
    int n_rows, double inv_n)
{
    const int tid   = blockIdx.x * blockDim.x + threadIdx.x;
    const int lane4 = tid & 3;
    const int group = tid >> 2;
    const int n_grp = (gridDim.x * blockDim.x) >> 2;

    float acc = 0.0f;

    // Prologue: load first row set (group < n_rows always for this size).
    size_t base = (size_t)group * 16 + (size_t)lane4 * 4;
    float4 w4 = *reinterpret_cast<const float4*>(weight + base);
    float4 l4 = *reinterpret_cast<const float4*>(loc    + base);
    float4 s4 = *reinterpret_cast<const float4*>(scale  + base);
    float  t  = __ldg(targets + group);

    for (int row = group; row < n_rows; row += n_grp) {
        // ---- prefetch next iteration (clamped-safe address when OOB) ----
        const int  nrow = row + n_grp;
        const bool hn   = nrow < n_rows;
        const int  prow = hn ? nrow : group;          // valid fallback addr
        const size_t nb = (size_t)prow * 16 + (size_t)lane4 * 4;
        const float4 nw = *reinterpret_cast<const float4*>(weight + nb);
        const float4 nl = *reinterpret_cast<const float4*>(loc    + nb);
        const float4 ns = *reinterpret_cast<const float4*>(scale  + nb);
        const float  nt = __ldg(targets + prow);

        // ---- compute current row ----
        const float w[4] = {w4.x, w4.y, w4.z, w4.w};
        const float l[4] = {l4.x, l4.y, l4.z, l4.w};
        const float s[4] = {s4.x, s4.y, s4.z, s4.w};

        float S1 = 0.0f, S2 = 0.0f;
        #pragma unroll
        for (int c = 0; c < 4; c++) {
            float rs = __fdividef(1.0f, s[c]);            // MUFU rcp
            float th = fast_tanh((t - l[c]) * rs * 0.5f); // MUFU tanh
            float ew = __expf(w[c]);                      // MUFU ex2
            S1 += ew;
            S2 = fmaf(ew * rs, fmaf(-th, th, 1.0f), S2);
        }

        // 4-lane group reductions (2 shuffle steps each).
        S1 += __shfl_xor_sync(0xffffffffu, S1, 1);
        S1 += __shfl_xor_sync(0xffffffffu, S1, 2);
        S2 += __shfl_xor_sync(0xffffffffu, S2, 1);
        S2 += __shfl_xor_sync(0xffffffffu, S2, 2);

        if (lane4 == 0) {
            S2 = fmaxf(S2, 1e-37f);                       // underflow guard
            acc += __logf(__fdividef(S2, S1)) - 1.3862943611f;   // - ln4
        }

        // ---- rotate prefetched registers in ----
        w4 = nw; l4 = nl; s4 = ns; t = nt;
    }

    // Warp reduction (only lane4==0 lanes hold nonzero partials).
    #pragma unroll
    for (int off = 16; off > 0; off >>= 1)
        acc += __shfl_xor_sync(0xffffffffu, acc, off);

    __shared__ float warp_part[8];
    const int warp = threadIdx.x >> 5;
    const int lane = threadIdx.x & 31;
    if (lane == 0) warp_part[warp] = acc;
    __syncthreads();

    if (warp == 0) {
        float v = (lane < (256 >> 5)) ? warp_part[lane] : 0.0f;
        #pragma unroll
        for (int off = 4; off > 0; off >>= 1)
            v += __shfl_xor_sync(0xffffffffu, v, off);

        if (lane == 0) {
            atomicAdd(&g_acc, (double)v);
            __threadfence();
            unsigned done = atomicAdd(&g_count, 1u);
            if (done == gridDim.x - 1) {
                out[0] = (float)(g_acc * inv_n);
                g_acc   = 0.0;     // reset for next deterministic replay
                g_count = 0u;
                __threadfence();
            }
        }
    }
}

extern "C" void kernel_launch(void* const* d_in, const int* in_sizes, int n_in,
                              void* d_out, int out_size) {
    const float* weight  = (const float*)d_in[0];
    const float* loc     = (const float*)d_in[1];
    const float* scale   = (const float*)d_in[2];
    const float* targets = (const float*)d_in[3];
    float* out = (float*)d_out;

    const int n_rows = in_sizes[3];          // B*T = 2,097,152
    const double inv_n = 1.0 / (double)n_rows;

    // One resident wave: 148 SMs x 5 blocks/SM (regs capped at 51).
    MixtureOfLogistics_kernel<<<740, 256>>>(weight, loc, scale, targets, out,
                                            n_rows, inv_n);
}